// round 13
// baseline (speedup 1.0000x reference)
#include <cuda_runtime.h>
#include <cuda_bf16.h>
#include <cstdint>

#define NN 50000
#define NE 800000
#define HC 128      // HEADS*HID = 4*32
#define NH 4
#define NOUT 32
#define NTILES 391  // ceil(NN/128)
#define SA 136      // padded bf16 row stride

// ------------------------- device scratch -------------------------
__device__ float g_hproj[(size_t)NN * HC];
__device__ float g_hskip[(size_t)NN * HC];
__device__ float g_hskip32[(size_t)NN * NOUT];
__device__ float g_als[(size_t)NN * NH];
__device__ float g_ald[(size_t)NN * NH];
__device__ int   g_deg[NN];
__device__ int   g_cursor[NN];
__device__ int   g_rowptr[NN + 1];
__device__ int   g_csr[NE];
__device__ __nv_bfloat16 g_Ahi[(size_t)NTILES * 128 * SA];
__device__ __nv_bfloat16 g_Alo[(size_t)NTILES * 128 * SA];
__device__ __nv_bfloat16 g_Bhi[3 * 256 * SA];
__device__ __nv_bfloat16 g_Blo[3 * 256 * SA];

#define SEL_HSKIP   2
#define SEL_HSKIP32 5
__device__ __forceinline__ const float* selbuf(int sel) {
    return (sel == SEL_HSKIP) ? g_hskip : g_hskip32;
}

// ------------------------- CSR build -------------------------
__global__ void zero_kernel() {
    int i = blockIdx.x * blockDim.x + threadIdx.x;
    if (i < NN) g_deg[i] = 0;
}
__global__ void count_kernel(const int* __restrict__ dst) {
    int i = blockIdx.x * blockDim.x + threadIdx.x;
    if (i < NE) atomicAdd(&g_deg[dst[i]], 1);
}
// single-block warp-shuffle scan; also seeds g_cursor with rowptr
__global__ void scan_kernel() {
    __shared__ int wsums[32];
    __shared__ int carry;
    int tid = threadIdx.x, lane = tid & 31, wid = tid >> 5;
    if (tid == 0) carry = 0;
    __syncthreads();
    for (int base = 0; base < NN; base += 1024) {
        int i = base + tid;
        int v = (i < NN) ? g_deg[i] : 0;
        int x = v;
#pragma unroll
        for (int o = 1; o < 32; o <<= 1) {
            int y = __shfl_up_sync(0xffffffffu, x, o);
            if (lane >= o) x += y;
        }
        if (lane == 31) wsums[wid] = x;
        __syncthreads();
        if (wid == 0) {
            int s = wsums[lane];
#pragma unroll
            for (int o = 1; o < 32; o <<= 1) {
                int y = __shfl_up_sync(0xffffffffu, s, o);
                if (lane >= o) s += y;
            }
            wsums[lane] = s;
        }
        __syncthreads();
        int wpre = (wid == 0) ? 0 : wsums[wid - 1];
        if (i < NN) {
            int rp = x + wpre + carry - v;
            g_rowptr[i] = rp;
            g_cursor[i] = rp;
        }
        __syncthreads();
        if (tid == 0) carry += wsums[31];
        __syncthreads();
    }
    if (threadIdx.x == 0) g_rowptr[NN] = carry;
}
__global__ void scatter_kernel(const int* __restrict__ src, const int* __restrict__ dst) {
    int i = blockIdx.x * blockDim.x + threadIdx.x;
    if (i < NE) {
        int pos = atomicAdd(&g_cursor[dst[i]], 1);
        g_csr[pos] = src[i];
    }
}

// ------------------------- operand image conversion -------------------------
__device__ __forceinline__ uint32_t pack_bf2(__nv_bfloat16 a, __nv_bfloat16 b) {
    return ((uint32_t)__bfloat16_as_ushort(b) << 16) | __bfloat16_as_ushort(a);
}
__global__ void convA_kernel(const float* __restrict__ src) {
    int idx = blockIdx.x * blockDim.x + threadIdx.x;
    if (idx >= NTILES * 128 * 32) return;
    int n = idx >> 5, c4 = (idx & 31) * 4;
    float4 v = (n < NN) ? *(const float4*)&src[(size_t)n * 128 + c4]
                        : make_float4(0.f, 0.f, 0.f, 0.f);
    float vv[4] = {v.x, v.y, v.z, v.w};
    __nv_bfloat16 hi[4], lo[4];
#pragma unroll
    for (int e = 0; e < 4; e++) {
        hi[e] = __float2bfloat16(vv[e]);
        lo[e] = __float2bfloat16(vv[e] - __bfloat162float(hi[e]));
    }
    size_t a = (size_t)n * SA + c4;
    *(uint2*)&g_Ahi[a] = make_uint2(pack_bf2(hi[0], hi[1]), pack_bf2(hi[2], hi[3]));
    *(uint2*)&g_Alo[a] = make_uint2(pack_bf2(lo[0], lo[1]), pack_bf2(lo[2], lo[3]));
}
// B image rows = output col n ([n][k]); n<128 -> W[k,n]; [128,nv) -> Ws[k,n-128]; [nv,nst) -> 0
__global__ void convB_kernel(const float* __restrict__ W, const float* __restrict__ Ws,
                             int ns, int n_valid, int n_stage, int layer) {
    int idx = blockIdx.x * blockDim.x + threadIdx.x;
    if (idx >= n_stage * 128) return;
    int n = idx >> 7, k = idx & 127;
    float v = 0.f;
    if (n < 128) v = W[(size_t)k * 128 + n];
    else if (n < n_valid) v = Ws[(size_t)k * ns + (n - 128)];
    size_t a = (size_t)layer * 256 * SA + (size_t)n * SA + k;
    __nv_bfloat16 hi = __float2bfloat16(v);
    g_Bhi[a] = hi;
    g_Blo[a] = __float2bfloat16(v - __bfloat162float(hi));
}

// ------------------------- bf16 split HMMA GEMM (ldmatrix, 64-col panels) -------------------------
__device__ __forceinline__ void mma16816(float* c, const uint32_t* a, const uint32_t* b) {
    asm volatile(
        "mma.sync.aligned.m16n8k16.row.col.f32.bf16.bf16.f32 "
        "{%0,%1,%2,%3}, {%4,%5,%6,%7}, {%8,%9}, {%0,%1,%2,%3};"
        : "+f"(c[0]), "+f"(c[1]), "+f"(c[2]), "+f"(c[3])
        : "r"(a[0]), "r"(a[1]), "r"(a[2]), "r"(a[3]), "r"(b[0]), "r"(b[1]));
}
__device__ __forceinline__ void ldsm4(uint32_t* r, const __nv_bfloat16* p) {
    uint32_t addr = (uint32_t)__cvta_generic_to_shared(p);
    asm volatile("ldmatrix.sync.aligned.m8n8.x4.shared.b16 {%0,%1,%2,%3}, [%4];"
                 : "=r"(r[0]), "=r"(r[1]), "=r"(r[2]), "=r"(r[3]) : "r"(addr));
}

// blockIdx.x = panel p. l2mode 0: p0,p1 proj / p2,p3 skip(128-wide). l2mode 1: p0,p1 proj / p2 skip32.
__global__ void __launch_bounds__(256, 2) bgemm64_kernel(
    const float* __restrict__ bias_skip,
    const float* __restrict__ aS, const float* __restrict__ aD,
    int l2mode, int layer, int M) {
    int p = blockIdx.x;
    int bOff, colOff, N, ncols;
    float* C;
    const float* bias;
    bool doAL;
    if (p < 2) {  // proj panels
        bOff = p * 64 * SA; C = g_hproj; colOff = p * 64; N = 128; ncols = 64;
        bias = nullptr; doAL = true;
    } else if (!l2mode) {  // skip panels, layers 0/1
        bOff = p * 64 * SA; C = g_hskip; colOff = (p - 2) * 64; N = 128; ncols = 64;
        bias = bias_skip + colOff; doAL = false;
    } else {  // skip panel, layer 2
        bOff = 128 * SA; C = g_hskip32; colOff = 0; N = 32; ncols = 32;
        bias = bias_skip; doAL = false;
    }
    bOff += layer * 256 * SA;

    extern __shared__ __nv_bfloat16 sm[];
    __nv_bfloat16* sAhi = sm;
    __nv_bfloat16* sAlo = sm + 128 * SA;
    __nv_bfloat16* sBhi = sm + 2 * 128 * SA;
    __nv_bfloat16* sBlo = sBhi + 64 * SA;

    int tid = threadIdx.x;
    int lane = tid & 31, w = tid >> 5;
    int m0 = blockIdx.y * 128;

    // stage: pure uint4 copies
    {
        const uint4* gAh = (const uint4*)(g_Ahi + (size_t)blockIdx.y * 128 * SA);
        const uint4* gAl = (const uint4*)(g_Alo + (size_t)blockIdx.y * 128 * SA);
        uint4* dAh = (uint4*)sAhi;
        uint4* dAl = (uint4*)sAlo;
#pragma unroll
        for (int i = tid; i < 128 * SA / 8; i += 256) { dAh[i] = gAh[i]; dAl[i] = gAl[i]; }
        const uint4* gBh = (const uint4*)(g_Bhi + bOff);
        const uint4* gBl = (const uint4*)(g_Blo + bOff);
        uint4* dBh = (uint4*)sBhi;
        uint4* dBl = (uint4*)sBlo;
#pragma unroll
        for (int i = tid; i < 64 * SA / 8; i += 256) { dBh[i] = gBh[i]; dBl[i] = gBl[i]; }
    }
    __syncthreads();

    int wm = w >> 1, wn = w & 1;
    int mo = wm * 32, no = wn * 32;
    int g = lane >> 2, t = lane & 3;

    // ldmatrix per-lane row/col constants
    int lm = lane >> 3, l7 = lane & 7;
    int rowA = (lm & 1) * 8 + l7, colA = (lm >> 1) * 8;   // A: matrices {r,r+8}x{k,k+8}
    int rowB = (lm >> 1) * 8 + l7, colB = (lm & 1) * 8;   // B: {b[2j][0],b[2j][1],b[2j+1][0],b[2j+1][1]}

    const __nv_bfloat16* pAhi = sAhi + (mo + rowA) * SA + colA;
    const __nv_bfloat16* pAlo = sAlo + (mo + rowA) * SA + colA;
    const __nv_bfloat16* pBhi = sBhi + (no + rowB) * SA + colB;
    const __nv_bfloat16* pBlo = sBlo + (no + rowB) * SA + colB;

    float acc[2][4][4] = {};

#pragma unroll
    for (int k0 = 0; k0 < 128; k0 += 16) {
        uint32_t ah[2][4], al_[2][4], bh[4][2], bl[4][2];
#pragma unroll
        for (int mt = 0; mt < 2; mt++) {
            ldsm4(ah[mt], pAhi + mt * 16 * SA + k0);
            ldsm4(al_[mt], pAlo + mt * 16 * SA + k0);
        }
#pragma unroll
        for (int j = 0; j < 2; j++) {
            ldsm4(&bh[2 * j][0], pBhi + j * 16 * SA + k0);
            ldsm4(&bl[2 * j][0], pBlo + j * 16 * SA + k0);
        }
#pragma unroll
        for (int mt = 0; mt < 2; mt++)
#pragma unroll
            for (int nt = 0; nt < 4; nt++) {
                mma16816(acc[mt][nt], ah[mt], bh[nt]);
                mma16816(acc[mt][nt], al_[mt], bh[nt]);
                mma16816(acc[mt][nt], ah[mt], bl[nt]);
            }
    }

    // epilogue: store C (+bias)
#pragma unroll
    for (int mt = 0; mt < 2; mt++) {
        int row = m0 + mo + mt * 16 + g;
#pragma unroll
        for (int nt = 0; nt < 4; nt++) {
            int cl = no + nt * 8 + 2 * t;
            if (cl >= ncols) continue;
            float b0 = 0.f, b1 = 0.f;
            if (bias) { b0 = __ldg(&bias[cl]); b1 = __ldg(&bias[cl + 1]); }
            if (row < M)
                *(float2*)&C[(size_t)row * N + colOff + cl] =
                    make_float2(acc[mt][nt][0] + b0, acc[mt][nt][1] + b1);
            if (row + 8 < M)
                *(float2*)&C[(size_t)(row + 8) * N + colOff + cl] =
                    make_float2(acc[mt][nt][2] + b0, acc[mt][nt][3] + b1);
        }
    }

    // fused attention logits: warp's 32 cols = head (colOff+no)/32
    if (doAL) {
        int head = (colOff + no) >> 5;
        float sS[2][2], sD[2][2];
#pragma unroll
        for (int mt = 0; mt < 2; mt++) { sS[mt][0] = sS[mt][1] = sD[mt][0] = sD[mt][1] = 0.f; }
#pragma unroll
        for (int nt = 0; nt < 4; nt++) {
            int col = colOff + no + nt * 8 + 2 * t;
            float c0s = __ldg(&aS[col]), c1s = __ldg(&aS[col + 1]);
            float c0d = __ldg(&aD[col]), c1d = __ldg(&aD[col + 1]);
#pragma unroll
            for (int mt = 0; mt < 2; mt++) {
                sS[mt][0] += acc[mt][nt][0] * c0s + acc[mt][nt][1] * c1s;
                sS[mt][1] += acc[mt][nt][2] * c0s + acc[mt][nt][3] * c1s;
                sD[mt][0] += acc[mt][nt][0] * c0d + acc[mt][nt][1] * c1d;
                sD[mt][1] += acc[mt][nt][2] * c0d + acc[mt][nt][3] * c1d;
            }
        }
#pragma unroll
        for (int mt = 0; mt < 2; mt++)
#pragma unroll
            for (int half = 0; half < 2; half++) {
                sS[mt][half] += __shfl_xor_sync(0xffffffffu, sS[mt][half], 1);
                sS[mt][half] += __shfl_xor_sync(0xffffffffu, sS[mt][half], 2);
                sD[mt][half] += __shfl_xor_sync(0xffffffffu, sD[mt][half], 1);
                sD[mt][half] += __shfl_xor_sync(0xffffffffu, sD[mt][half], 2);
            }
        if (t == 0) {
#pragma unroll
            for (int mt = 0; mt < 2; mt++) {
                int row = m0 + mo + mt * 16 + g;
                if (row < M) { g_als[(size_t)row * 4 + head] = sS[mt][0]; g_ald[(size_t)row * 4 + head] = sD[mt][0]; }
                if (row + 8 < M) { g_als[(size_t)(row + 8) * 4 + head] = sS[mt][1]; g_ald[(size_t)(row + 8) * 4 + head] = sD[mt][1]; }
            }
        }
    }
}

__device__ __forceinline__ float lrelu(float x) { return x > 0.f ? x : 0.2f * x; }

// ------------------------- aggregation (SINGLE sweep: unnormalized gather, divide at end) -------------------------
__global__ void agg_kernel(int skipsel, const float* __restrict__ bias,
                           float* __restrict__ outp, int mode) {
    const float* hskip = selbuf(skipsel);
    const int WPB = 8;
    __shared__ float sh_ex[WPB][32][4];
    __shared__ int sh_src[WPB][32];
    int w = threadIdx.x >> 5;
    int lane = threadIdx.x & 31;
    int n = blockIdx.x * WPB + w;
    if (n >= NN) return;
    int beg = g_rowptr[n], end = g_rowptr[n + 1];
    float4 ad = *(const float4*)&g_ald[(size_t)n * 4];

    // single sweep: accumulate Σexp (per head) and Σexp·h (unnormalized) together
    int hsel = lane >> 3;
    float s0 = 0.f, s1 = 0.f, s2 = 0.f, s3 = 0.f;
    float4 acc = make_float4(0.f, 0.f, 0.f, 0.f);
    for (int base = beg; base < end; base += 32) {
        int j = base + lane;
        if (j < end) {
            int sr = g_csr[j];
            sh_src[w][lane] = sr;
            float4 a = __ldg((const float4*)&g_als[(size_t)sr * 4]);
            float e0 = __expf(lrelu(a.x + ad.x));
            float e1 = __expf(lrelu(a.y + ad.y));
            float e2 = __expf(lrelu(a.z + ad.z));
            float e3 = __expf(lrelu(a.w + ad.w));
            sh_ex[w][lane][0] = e0;
            sh_ex[w][lane][1] = e1;
            sh_ex[w][lane][2] = e2;
            sh_ex[w][lane][3] = e3;
            s0 += e0; s1 += e1; s2 += e2; s3 += e3;
        }
        __syncwarp();
        int cnt = min(32, end - base);
#pragma unroll 4
        for (int k = 0; k < cnt; k++) {
            int sr = sh_src[w][k];
            float av = sh_ex[w][k][hsel];
            float4 hv = *(const float4*)&g_hproj[(size_t)sr * HC + 4 * lane];
            acc.x += av * hv.x;
            acc.y += av * hv.y;
            acc.z += av * hv.z;
            acc.w += av * hv.w;
        }
        __syncwarp();
    }
    // reduce denominators across warp, pick this lane's head
#pragma unroll
    for (int o = 16; o > 0; o >>= 1) {
        s0 += __shfl_xor_sync(0xffffffffu, s0, o);
        s1 += __shfl_xor_sync(0xffffffffu, s1, o);
        s2 += __shfl_xor_sync(0xffffffffu, s2, o);
        s3 += __shfl_xor_sync(0xffffffffu, s3, o);
    }
    float sh = (hsel == 0) ? s0 : (hsel == 1) ? s1 : (hsel == 2) ? s2 : s3;
    float inv = 1.f / (sh + 1e-16f);
    acc.x *= inv; acc.y *= inv; acc.z *= inv; acc.w *= inv;

    if (mode == 0) {
        float4 bb = __ldg((const float4*)&bias[4 * lane]);
        float4 sk = *(const float4*)&hskip[(size_t)n * HC + 4 * lane];
        float v[4] = {acc.x + bb.x + sk.x, acc.y + bb.y + sk.y,
                      acc.z + bb.z + sk.z, acc.w + bb.w + sk.w};
        __nv_bfloat16 hi[4], lo[4];
#pragma unroll
        for (int e = 0; e < 4; e++) {
            v[e] = v[e] > 0.f ? v[e] : expm1f(v[e]);
            hi[e] = __float2bfloat16(v[e]);
            lo[e] = __float2bfloat16(v[e] - __bfloat162float(hi[e]));
        }
        size_t a = (size_t)n * SA + 4 * lane;
        *(uint2*)&g_Ahi[a] = make_uint2(pack_bf2(hi[0], hi[1]), pack_bf2(hi[2], hi[3]));
        *(uint2*)&g_Alo[a] = make_uint2(pack_bf2(lo[0], lo[1]), pack_bf2(lo[2], lo[3]));
    } else {
        // head-mean: sum over lanes {L, L^8, L^16, L^24}
#pragma unroll
        for (int o = 8; o <= 16; o <<= 1) {
            acc.x += __shfl_xor_sync(0xffffffffu, acc.x, o);
            acc.y += __shfl_xor_sync(0xffffffffu, acc.y, o);
            acc.z += __shfl_xor_sync(0xffffffffu, acc.z, o);
            acc.w += __shfl_xor_sync(0xffffffffu, acc.w, o);
        }
        int cc = 4 * (lane & 7);
        float4 bb = __ldg((const float4*)&bias[cc]);
        float4 sk = *(const float4*)&hskip[(size_t)n * NOUT + cc];
        float v[4] = {0.25f * acc.x + bb.x + sk.x, 0.25f * acc.y + bb.y + sk.y,
                      0.25f * acc.z + bb.z + sk.z, 0.25f * acc.w + bb.w + sk.w};
        float ss = v[0] * v[0] + v[1] * v[1] + v[2] * v[2] + v[3] * v[3];
#pragma unroll
        for (int o = 1; o <= 4; o <<= 1) ss += __shfl_xor_sync(0xffffffffu, ss, o);
        float r = fmaxf(sqrtf(ss), 1e-12f);
        if (lane < 8)
            *(float4*)&outp[(size_t)n * NOUT + cc] =
                make_float4(v[0] / r, v[1] / r, v[2] / r, v[3] / r);
    }
}

// ------------------------- launch -------------------------
extern "C" void kernel_launch(void* const* d_in, const int* in_sizes, int n_in,
                              void* d_out, int out_size) {
    const float* x = (const float*)d_in[0];
    const int* ei = (const int*)d_in[1];
    const int* src = ei;
    const int* dst = ei + NE;
    const float* W0 = (const float*)d_in[2];
    const float* aS0 = (const float*)d_in[3];
    const float* aD0 = (const float*)d_in[4];
    const float* b0 = (const float*)d_in[5];
    const float* Ws0 = (const float*)d_in[6];
    const float* bs0 = (const float*)d_in[7];
    const float* W1 = (const float*)d_in[8];
    const float* aS1 = (const float*)d_in[9];
    const float* aD1 = (const float*)d_in[10];
    const float* b1 = (const float*)d_in[11];
    const float* Ws1 = (const float*)d_in[12];
    const float* bs1 = (const float*)d_in[13];
    const float* W2 = (const float*)d_in[14];
    const float* aS2 = (const float*)d_in[15];
    const float* aD2 = (const float*)d_in[16];
    const float* b2 = (const float*)d_in[17];
    const float* Ws2 = (const float*)d_in[18];
    const float* bs2 = (const float*)d_in[19];
    float* out = (float*)d_out;

    const int SMEM_GEMM = (2 * 128 * SA + 2 * 64 * SA) * 2;  // 104448

    // one-time setup (first call is the non-capturing correctness run)
    static cudaStream_t side = nullptr;
    static cudaEvent_t evFork = nullptr, evJoin = nullptr;
    static bool inited = false;
    if (!inited) {
        cudaFuncSetAttribute(bgemm64_kernel, cudaFuncAttributeMaxDynamicSharedMemorySize, SMEM_GEMM);
        cudaStreamCreateWithFlags(&side, cudaStreamNonBlocking);
        cudaEventCreateWithFlags(&evFork, cudaEventDisableTiming);
        cudaEventCreateWithFlags(&evJoin, cudaEventDisableTiming);
        inited = true;
    }

    int aggBlocks = (NN + 7) / 8;

    // ---- fork: CSR build on side stream, overlapped with conv + layer-0 GEMM ----
    cudaEventRecord(evFork, 0);
    cudaStreamWaitEvent(side, evFork, 0);
    zero_kernel<<<(NN + 255) / 256, 256, 0, side>>>();
    count_kernel<<<(NE + 255) / 256, 256, 0, side>>>(dst);
    scan_kernel<<<1, 1024, 0, side>>>();
    scatter_kernel<<<(NE + 255) / 256, 256, 0, side>>>(src, dst);
    cudaEventRecord(evJoin, side);

    // main stream: conversions + layer-0 GEMM (independent of CSR)
    convA_kernel<<<(NTILES * 128 * 32 + 255) / 256, 256>>>(x);
    convB_kernel<<<(256 * 128 + 255) / 256, 256>>>(W0, Ws0, 128, 256, 256, 0);
    convB_kernel<<<(256 * 128 + 255) / 256, 256>>>(W1, Ws1, 128, 256, 256, 1);
    convB_kernel<<<(192 * 128 + 255) / 256, 256>>>(W2, Ws2, 32, 160, 192, 2);
    bgemm64_kernel<<<dim3(4, NTILES), 256, SMEM_GEMM>>>(bs0, aS0, aD0, 0, 0, NN);

    // join: agg needs CSR
    cudaStreamWaitEvent(0, evJoin, 0);
    agg_kernel<<<aggBlocks, 256>>>(SEL_HSKIP, b0, nullptr, 0);

    // ---- layer 1 ----
    bgemm64_kernel<<<dim3(4, NTILES), 256, SMEM_GEMM>>>(bs1, aS1, aD1, 0, 1, NN);
    agg_kernel<<<aggBlocks, 256>>>(SEL_HSKIP, b1, nullptr, 0);

    // ---- layer 2 ----
    bgemm64_kernel<<<dim3(3, NTILES), 256, SMEM_GEMM>>>(bs2, aS2, aD2, 1, 2, NN);
    agg_kernel<<<aggBlocks, 256>>>(SEL_HSKIP32, b2, out, 1);
}